// round 16
// baseline (speedup 1.0000x reference)
#include <cuda_runtime.h>
#include <cuda_bf16.h>
#include <cuda_fp16.h>
#include <math.h>
#include <stdint.h>

#define NNODE 256
#define NCLUS 128
#define NEDGE 4096
#define MARGIN 32768   // fp16 elems of slack on both sides of activation planes

// ---------------------------------------------------------------------------
// Scratch (device globals). Zero-initialized at module load; pad rings and
// margins are NEVER written. g_adj / g_scal are re-zeroed by their last
// consumers each replay, so every replay starts from the same state.
// ---------------------------------------------------------------------------
__device__ __align__(16) __half g_a1[2228224];   // 258^2*32 + margins
__device__ __align__(16) __half g_a2[1150000];   // 130^2*64 + margins
__device__ __align__(16) __half g_a3[625000];    // 66^2*128 + margins
__device__ __align__(16) __half g_a4[365000];    // 34^2*256 + margins
__device__ __align__(16) __half g_wph[980000];
__device__ __align__(16) float g_D[4194304];     // split-K partials (16.8 MB)
__device__ float g_org[NNODE * NNODE];
__device__ float g_adj[NNODE * NNODE];
__device__ float g_ssoft[NNODE * NCLUS];
__device__ float g_ssoftT[NCLUS * NNODE];
__device__ float g_x1[NNODE * 2];
__device__ float g_tmp[NNODE * NCLUS];
__device__ float g_nodes[NCLUS * 2];
__device__ float g_ebin[NCLUS * NCLUS];
__device__ float g_scal[2];

// ---------------------------------------------------------------------------
// Warp MMA helpers (plain PTX; works on sm_100 non-'a' target)
// ---------------------------------------------------------------------------
__device__ __forceinline__ void ldsm4(uint32_t* r, uint32_t a) {
    asm volatile("ldmatrix.sync.aligned.m8n8.x4.shared.b16 {%0,%1,%2,%3}, [%4];"
                 : "=r"(r[0]), "=r"(r[1]), "=r"(r[2]), "=r"(r[3]) : "r"(a));
}
__device__ __forceinline__ void mma16816(float* d, const uint32_t* a,
                                         uint32_t b0, uint32_t b1) {
    asm volatile(
        "mma.sync.aligned.m16n8k16.row.col.f32.f16.f16.f32 "
        "{%0,%1,%2,%3}, {%4,%5,%6,%7}, {%8,%9}, {%0,%1,%2,%3};"
        : "+f"(d[0]), "+f"(d[1]), "+f"(d[2]), "+f"(d[3])
        : "r"(a[0]), "r"(a[1]), "r"(a[2]), "r"(a[3]), "r"(b0), "r"(b1));
}
__device__ __forceinline__ uint32_t s2u(const void* p) {
    uint32_t a;
    asm("{ .reg .u64 t; cvta.to.shared.u64 t, %1; cvt.u32.u64 %0, t; }"
        : "=r"(a) : "l"(p));
    return a;
}

// ---------------------------------------------------------------------------
// L1: direct conv 3->32, 512x512, fused bias+relu+pool, padded HWC fp16 out
// ---------------------------------------------------------------------------
__global__ void __launch_bounds__(256, 2)
conv1_k(const float* __restrict__ in, const float* __restrict__ w,
        const float* __restrict__ bias, __half* __restrict__ oh) {
    const int H = 512, W = 512;
    __shared__ float s_in[3 * 1156];
    __shared__ float s_w[3 * 16 * 12];
    const int tid = threadIdx.x, tx = tid & 15, ty = tid >> 4;
    const int ox0 = blockIdx.x * 16, oy0 = blockIdx.y * 16;
    const int co0 = blockIdx.z * 16;
    const int ix0 = 2 * ox0 - 1, iy0 = 2 * oy0 - 1;

    for (int i = tid; i < 16 * 27; i += 256) {
        int co = i / 27, rem = i - co * 27, ci = rem / 9, t = rem - ci * 9;
        s_w[(ci * 16 + co) * 12 + t] = w[((co0 + co) * 3 + ci) * 9 + t];
    }
    for (int ci = 0; ci < 3; ++ci) {
        const float* inp = in + ci * H * W;
        for (int i = tid; i < 1156; i += 256) {
            int r = i / 34, c = i - r * 34;
            int gy = iy0 + r, gx = ix0 + c;
            s_in[ci * 1156 + i] =
                (gy >= 0 && gy < H && gx >= 0 && gx < W) ? inp[gy * W + gx] : 0.f;
        }
    }
    __syncthreads();

    float acc[16][4];
#pragma unroll
    for (int co = 0; co < 16; ++co)
#pragma unroll
        for (int q = 0; q < 4; ++q) acc[co][q] = 0.f;

    const int base = (2 * ty) * 34 + 2 * tx;
#pragma unroll
    for (int ci = 0; ci < 3; ++ci) {
        float p[16];
        const float* sp = s_in + ci * 1156 + base;
#pragma unroll
        for (int r = 0; r < 4; ++r)
#pragma unroll
            for (int c = 0; c < 4; ++c) p[r * 4 + c] = sp[r * 34 + c];
#pragma unroll
        for (int co = 0; co < 16; ++co) {
            const float* wp = &s_w[(ci * 16 + co) * 12];
#pragma unroll
            for (int ky = 0; ky < 3; ++ky)
#pragma unroll
                for (int kx = 0; kx < 3; ++kx) {
                    float wv = wp[ky * 3 + kx];
#pragma unroll
                    for (int dy = 0; dy < 2; ++dy)
#pragma unroll
                        for (int dx = 0; dx < 2; ++dx)
                            acc[co][dy * 2 + dx] += wv * p[(dy + ky) * 4 + (dx + kx)];
                }
        }
    }

    const long pix = ((long)(oy0 + ty + 1) * 258 + (ox0 + tx + 1)) * 32;
#pragma unroll
    for (int co = 0; co < 16; ++co) {
        float m = fmaxf(fmaxf(acc[co][0], acc[co][1]),
                        fmaxf(acc[co][2], acc[co][3]));
        oh[pix + co0 + co] = __float2half(fmaxf(m + bias[co0 + co], 0.f));
    }
}

// ---------------------------------------------------------------------------
// Fused weight pack for w2..w5 (+ adjacency build in trailing blocks).
// ---------------------------------------------------------------------------
__global__ void k_packall(const float* __restrict__ w2, const float* __restrict__ w3,
                          const float* __restrict__ w4, const float* __restrict__ w5,
                          __half* __restrict__ wh, const int* __restrict__ ei) {
    if (blockIdx.x >= 3816) {   // adjacency build (16 blocks)
        int e = (blockIdx.x - 3816) * 256 + threadIdx.x;
        if (e < NEDGE)
            atomicAdd(&g_adj[ei[e] * NNODE + ei[NEDGE + e]], 1.f);
        return;
    }
    int idx = blockIdx.x * 256 + threadIdx.x;
    if (idx >= 976896) return;
    const float* w; int CIN, LGC, base;
    if (idx < 18432)      { w = w2; CIN = 32;  LGC = 5; base = 0; }
    else if (idx < 92160) { w = w3; CIN = 64;  LGC = 6; base = 18432; }
    else if (idx < 387072){ w = w4; CIN = 128; LGC = 7; base = 92160; }
    else                  { w = w5; CIN = 256; LGC = 8; base = 387072; }
    int local = idx - base;
    int KTOT = 9 * CIN;
    int co = local / KTOT, kc = local - co * KTOT;
    int k = kc >> LGC, ci = kc & (CIN - 1);
    wh[idx] = __float2half(w[((size_t)co * CIN + ci) * 9 + k]);
}

// ---------------------------------------------------------------------------
// Implicit-GEMM conv via single fp16 mma.sync, 32-K chunks.
// OUTM=0: fused bias+relu+pool -> fp16 padded HWC (NS==1)
// OUTM=2: split-K raw fp32 partials -> forg[z][m][n]
// ---------------------------------------------------------------------------
template <int CIN, int LGC, int OUTM, int NS>
__global__ void __launch_bounds__(256, 2)
gemm_conv(const __half* __restrict__ ah, const __half* __restrict__ wh,
          const float* __restrict__ bias,
          __half* __restrict__ oh, float* __restrict__ forg,
          int Wp, int W2, int lg, int coutTot, int mtot) {
    constexpr int KTOT = 9 * CIN;
    constexpr int NCHUNK = KTOT / 32;
    constexpr int NCH = NCHUNK / NS;
    constexpr int ASZ = 128 * 80, BSZ = 64 * 80;
    constexpr int STG = ASZ + BSZ;       // 15360 per stage

    extern __shared__ __align__(16) char smc[];
    const uint32_t sb = s2u(smc);
    const int tid = threadIdx.x, lid = tid & 31, wid = tid >> 5;
    const int wmi = wid & 3, wni = wid >> 2;
    const int p0 = blockIdx.x * 128, n0 = blockIdx.y * 64;
    const int c0 = (NS > 1) ? blockIdx.z * NCH : 0;

    const int arow = tid >> 2, au = tid & 3;
    const uint32_t soA = arow * 80 + au * 16;

    const int mat = lid >> 3, i8 = lid & 7;
    const int mrow0 = wmi * 32 + (mat & 1) * 8 + i8;
    const int nrow0 = wni * 32 + (mat & 1) * 8 + i8;
    const int cu = mat >> 1;

    auto rowbase = [&](int m) -> long {
        int q = m >> 2, dy = (m >> 1) & 1, dx = m & 1;
        int py = q >> lg, px = q & (W2 - 1);
        return ((long)(2 * py + 1 + dy) * Wp + (2 * px + 1 + dx)) * CIN;
    };
    const long rb0 = rowbase(p0 + arow);
    const long rb1 = rowbase(p0 + arow + 64);
    const long wbase = (long)(n0 + arow) * KTOT + au * 8;

    float acc[2][4][4];
#pragma unroll
    for (int t = 0; t < 2; ++t)
#pragma unroll
        for (int j = 0; j < 4; ++j)
#pragma unroll
            for (int q = 0; q < 4; ++q) acc[t][j][q] = 0.f;

    uint4 rg[3];
    auto fetch = [&](int chunk) {
        const int kc0 = chunk * 32;
        const int kc = kc0 + au * 8;
        const int k = kc >> LGC;
        const int ci = kc & (CIN - 1);
        const long nb = ((long)(k / 3 - 1) * Wp + (k % 3 - 1)) * CIN + ci;
        rg[0] = *(const uint4*)(ah + rb0 + nb);
        rg[1] = *(const uint4*)(ah + rb1 + nb);
        rg[2] = *(const uint4*)(wh + wbase + kc0);
    };
    auto store = [&](int s) {
        char* d = smc + s * STG;
        *(uint4*)(d + soA) = rg[0];
        *(uint4*)(d + soA + 64 * 80) = rg[1];
        *(uint4*)(d + ASZ + soA) = rg[2];
    };
    auto compute = [&](int s) {
        const uint32_t base = sb + s * STG;
#pragma unroll
        for (int ks = 0; ks < 2; ++ks) {
            const uint32_t ucol = (ks * 2 + cu) * 16;
            uint32_t fah[2][4], fbh[2][4];
#pragma unroll
            for (int t = 0; t < 2; ++t)
                ldsm4(fah[t], base + (mrow0 + t * 16) * 80 + ucol);
#pragma unroll
            for (int j = 0; j < 2; ++j)
                ldsm4(fbh[j], base + ASZ + (nrow0 + j * 16) * 80 + ucol);
#pragma unroll
            for (int t = 0; t < 2; ++t)
#pragma unroll
                for (int j = 0; j < 2; ++j)
#pragma unroll
                    for (int sbi = 0; sbi < 2; ++sbi)
                        mma16816(acc[t][j * 2 + sbi], fah[t],
                                 fbh[j][sbi], fbh[j][sbi + 2]);
        }
    };

    fetch(c0);
    store(0);
    __syncthreads();
    for (int c = 0; c < NCH; ++c) {
        const bool more = (c + 1 < NCH);
        if (more) fetch(c0 + c + 1);
        compute(c & 1);
        if (more) store((c + 1) & 1);
        __syncthreads();
    }

    if (OUTM == 0) {
        const int cq = (lid & 3) * 2;
        const bool wlane = (lid & 12) == 0;
        const int qsub = lid >> 4;
#pragma unroll
        for (int j = 0; j < 4; ++j) {
            const int co = n0 + wni * 32 + j * 8 + cq;
            const float b0 = bias[co], b1 = bias[co + 1];
#pragma unroll
            for (int t = 0; t < 2; ++t) {
                float v[4];
#pragma unroll
                for (int q = 0; q < 4; ++q) {
                    float x = acc[t][j][q];
                    x = fmaxf(x, __shfl_xor_sync(0xffffffffu, x, 4));
                    x = fmaxf(x, __shfl_xor_sync(0xffffffffu, x, 8));
                    v[q] = x;
                }
                if (wlane) {
                    const int Pb = (p0 >> 2) + wmi * 8 + t * 4 + qsub;
                    float r0 = fmaxf(v[0] + b0, 0.f);
                    float r1 = fmaxf(v[1] + b1, 0.f);
                    float r2 = fmaxf(v[2] + b0, 0.f);
                    float r3 = fmaxf(v[3] + b1, 0.f);
                    int py = Pb >> lg, px = Pb & (W2 - 1);
                    long o = ((long)(py + 1) * (W2 + 2) + px + 1) * coutTot + co;
                    oh[o] = __float2half(r0);
                    oh[o + 1] = __float2half(r1);
                    int P2 = Pb + 2;
                    int py2 = P2 >> lg, px2 = P2 & (W2 - 1);
                    long o2 = ((long)(py2 + 1) * (W2 + 2) + px2 + 1) * coutTot + co;
                    oh[o2] = __float2half(r2);
                    oh[o2 + 1] = __float2half(r3);
                }
            }
        }
    } else {
        const int r = lid >> 2, cq = (lid & 3) * 2;
        float* dp = forg + (long)blockIdx.z * mtot * coutTot;
#pragma unroll
        for (int t = 0; t < 2; ++t) {
            const long row = p0 + wmi * 32 + t * 16 + r;
#pragma unroll
            for (int j = 0; j < 4; ++j) {
                float* bp = dp + row * coutTot + n0 + wni * 32 + j * 8 + cq;
                *(float2*)bp = make_float2(acc[t][j][0], acc[t][j][1]);
                *(float2*)(bp + 8L * coutTot) = make_float2(acc[t][j][2], acc[t][j][3]);
            }
        }
    }
}

// ---------------------------------------------------------------------------
// Split-K reduce + pool + bias + relu (outm=0 fp16 HWC; outm=1 fp32 org)
// ---------------------------------------------------------------------------
__global__ void __launch_bounds__(256)
k_redpool(const float* __restrict__ D, const float* __restrict__ bias,
          __half* __restrict__ oh, float* __restrict__ org,
          int cout, int npix, int W2, int lg, int ns, int outm) {
    int idx = blockIdx.x * 256 + threadIdx.x;
    if (idx >= npix * cout) return;
    int co = idx & (cout - 1);
    int q = idx / cout;
    long Mtot = (long)npix * 4;
    float v[4];
#pragma unroll
    for (int k = 0; k < 4; ++k) {
        float s = 0.f;
        for (int z = 0; z < ns; ++z)
            s += D[z * Mtot * cout + (long)(4 * q + k) * cout + co];
        v[k] = s;
    }
    float m = fmaxf(fmaxf(v[0], v[1]), fmaxf(v[2], v[3]));
    float r = fmaxf(m + bias[co], 0.f);
    if (outm == 0) {
        int py = q >> lg, px = q & (W2 - 1);
        oh[((long)(py + 1) * (W2 + 2) + px + 1) * cout + co] = __float2half(r);
    } else {
        org[co * 256 + q] = r;
    }
}

// ---------------------------------------------------------------------------
// Graph stage
// ---------------------------------------------------------------------------

// Fused per-node-row stage: sparse mean-agg -> SAGE2+softmax+entropy -> SAGE1.
__global__ void __launch_bounds__(256)
k_rowstage(const float* __restrict__ org,
           const float* __restrict__ wl1, const float* __restrict__ wr1,
           const float* __restrict__ b1v,
           const float* __restrict__ wl2, const float* __restrict__ wr2,
           const float* __restrict__ b2v) {
    __shared__ float sAgg[256], sOrg[256], sv[256], red[128], sx[4];
    const int i = blockIdx.x, t = threadIdx.x;
    sOrg[t] = org[i * 256 + t];
    float tot = 0.f, cnt = 0.f;
    for (int s = 0; s < 256; ++s) {
        float a = g_adj[s * 256 + i];   // broadcast load
        if (a != 0.f) {
            tot += a * org[s * 256 + t];
            cnt += a;
        }
    }
    sAgg[t] = (cnt > 0.f) ? tot / cnt : 0.f;
    __syncthreads();

    const int j = t & 127, h = t >> 7;
    float v = 0.f;
    for (int k = h * 128; k < h * 128 + 128; ++k)
        v += sAgg[k] * wl2[k * 128 + j] + sOrg[k] * wr2[k * 128 + j];
    sv[t] = v;
    __syncthreads();

    float lv = (t < 128) ? sv[t] + sv[t + 128] + b2v[t] : -1e30f;
    if (t >= 128 && t < 132) {
        int jj = (t - 128) & 1, hh = (t - 128) >> 1;
        float xv = 0.f;
        for (int k = hh * 128; k < hh * 128 + 128; ++k)
            xv += sAgg[k] * wl1[k * 2 + jj] + sOrg[k] * wr1[k * 2 + jj];
        sx[t - 128] = xv;
    }

    if (t < 128) red[t] = lv;
    __syncthreads();
    for (int off = 64; off > 0; off >>= 1) {
        if (t < off) red[t] = fmaxf(red[t], red[t + off]);
        __syncthreads();
    }
    float m = red[0];
    __syncthreads();
    float e = (t < 128) ? expf(lv - m) : 0.f;
    if (t < 128) red[t] = e;
    __syncthreads();
    for (int off = 64; off > 0; off >>= 1) {
        if (t < off) red[t] += red[t + off];
        __syncthreads();
    }
    float denom = red[0];
    __syncthreads();
    float p = e / denom;
    if (t < 128) {
        g_ssoft[i * 128 + t] = p;
        g_ssoftT[t * 256 + i] = p;
        red[t] = -p * logf(p + 1e-15f);
    }
    __syncthreads();
    for (int off = 64; off > 0; off >>= 1) {
        if (t < off) red[t] += red[t + off];
        __syncthreads();
    }
    if (t == 0) atomicAdd(&g_scal[1], red[0]);
    if (t < 2) g_x1[i * 2 + t] = sx[t] + sx[t + 2] + b1v[t];
}

// Fused: tmp row i (sparse adj@ssoft) + link-loss row i (coalesced via ssoftT);
// zeroes adj row i for the next replay.
__global__ void __launch_bounds__(256) k_tmplink() {
    __shared__ float rowA[256], rowS[128], red[256];
    const int i = blockIdx.x, t = threadIdx.x;
    rowA[t] = g_adj[i * NNODE + t];
    if (t < 128) rowS[t] = g_ssoft[i * NCLUS + t];
    __syncthreads();
    g_adj[i * NNODE + t] = 0.f;   // self-clean for next replay

    float d = 0.f;
    for (int c = 0; c < NCLUS; ++c)
        d += rowS[c] * g_ssoftT[c * 256 + t];
    float diff = rowA[t] - d;
    red[t] = diff * diff;

    if (t < 128) {
        float v = 0.f;
        for (int k = 0; k < NNODE; ++k) {
            float a = rowA[k];
            if (a != 0.f) v += a * g_ssoft[k * NCLUS + t];
        }
        g_tmp[i * NCLUS + t] = v;
    }
    __syncthreads();
    for (int off = 128; off > 0; off >>= 1) {
        if (t < off) red[t] += red[t + off];
        __syncthreads();
    }
    if (t == 0) atomicAdd(&g_scal[0], red[0]);
}

// Fused: adjpool row r -> rowmax -> edge_bin; + xpool column r -> nodes
__global__ void __launch_bounds__(128) k_adjebin(float* __restrict__ dout) {
    const int r = blockIdx.x, c = threadIdx.x;
    float v = 0.f;
    for (int i = 0; i < NNODE; ++i)
        v += g_ssoftT[r * 256 + i] * g_tmp[i * NCLUS + c];
    __shared__ float red[128], r0[128], r1[128];
    float p0 = 0.f, p1 = 0.f;
    for (int i = c; i < NNODE; i += 128) {
        float s = g_ssoftT[r * 256 + i];
        p0 += s * g_x1[i * 2];
        p1 += s * g_x1[i * 2 + 1];
    }
    r0[c] = p0; r1[c] = p1;
    red[c] = v;
    __syncthreads();
    for (int off = 64; off > 0; off >>= 1) {
        if (c < off) {
            red[c] = fmaxf(red[c], red[c + off]);
            r0[c] += r0[c + off];
            r1[c] += r1[c + off];
        }
        __syncthreads();
    }
    float eb = (v == red[0]) ? 1.f : 0.f;
    g_ebin[r * NCLUS + c] = eb;
    dout[514 + r * NCLUS + c] = eb;
    if (c == 0) {
        float n0 = tanhf(r0[0]), n1 = tanhf(r1[0]);
        g_nodes[r * 2] = n0; g_nodes[r * 2 + 1] = n1;
        dout[258 + r * 2] = n0; dout[258 + r * 2 + 1] = n1;
    }
}

__global__ void __launch_bounds__(128) k_final(const float* __restrict__ wl,
                                               const float* __restrict__ wr,
                                               const float* __restrict__ bb,
                                               float* __restrict__ dout) {
    int c = threadIdx.x;
    float ind = 0.f, a0 = 0.f, a1 = 0.f;
    for (int r = 0; r < NCLUS; ++r) {
        float e = g_ebin[r * NCLUS + c];
        ind += e;
        a0 += e * g_nodes[r * 2];
        a1 += e * g_nodes[r * 2 + 1];
    }
    if (ind > 0.f) { a0 /= ind; a1 /= ind; } else { a0 = 0.f; a1 = 0.f; }
    float n0 = g_nodes[c * 2], n1 = g_nodes[c * 2 + 1];
#pragma unroll
    for (int j = 0; j < 2; ++j) {
        float o = a0 * wl[j] + a1 * wl[2 + j] + bb[j] + n0 * wr[j] + n1 * wr[2 + j];
        dout[c * 2 + j] = o;
    }
    if (c == 0) {
        dout[256] = sqrtf(g_scal[0]) / 65536.f;
        dout[257] = g_scal[1] / 256.f;
        g_scal[0] = 0.f;   // self-clean for next replay
        g_scal[1] = 0.f;
    }
}

// ---------------------------------------------------------------------------
extern "C" void kernel_launch(void* const* d_in, const int* in_sizes, int n_in,
                              void* d_out, int out_size) {
    const float* x    = (const float*)d_in[0];
    const int*   ei   = (const int*)d_in[1];
    const float* w1   = (const float*)d_in[2];
    const float* b1   = (const float*)d_in[3];
    const float* w2   = (const float*)d_in[4];
    const float* b2   = (const float*)d_in[5];
    const float* w3   = (const float*)d_in[6];
    const float* b3   = (const float*)d_in[7];
    const float* w4   = (const float*)d_in[8];
    const float* b4   = (const float*)d_in[9];
    const float* w5   = (const float*)d_in[10];
    const float* b5   = (const float*)d_in[11];
    const float* s1wl = (const float*)d_in[12];
    const float* s1wr = (const float*)d_in[13];
    const float* s1b  = (const float*)d_in[14];
    const float* s2wl = (const float*)d_in[15];
    const float* s2wr = (const float*)d_in[16];
    const float* s2b  = (const float*)d_in[17];
    const float* s3wl = (const float*)d_in[18];
    const float* s3wr = (const float*)d_in[19];
    const float* s3b  = (const float*)d_in[20];
    float* dout = (float*)d_out;

    __half *a1, *a2, *a3, *a4, *wph;
    float *org, *D;
    cudaGetSymbolAddress((void**)&a1, g_a1);
    cudaGetSymbolAddress((void**)&a2, g_a2);
    cudaGetSymbolAddress((void**)&a3, g_a3);
    cudaGetSymbolAddress((void**)&a4, g_a4);
    cudaGetSymbolAddress((void**)&wph, g_wph);
    cudaGetSymbolAddress((void**)&org, g_org);
    cudaGetSymbolAddress((void**)&D, g_D);

    const int SMEM = 2 * (128 * 80 + 64 * 80);   // 30720 (2 stages)
    cudaFuncSetAttribute(gemm_conv<32, 5, 0, 1>,
                         cudaFuncAttributeMaxDynamicSharedMemorySize, SMEM);
    cudaFuncSetAttribute(gemm_conv<64, 6, 2, 2>,
                         cudaFuncAttributeMaxDynamicSharedMemorySize, SMEM);
    cudaFuncSetAttribute(gemm_conv<128, 7, 2, 4>,
                         cudaFuncAttributeMaxDynamicSharedMemorySize, SMEM);
    cudaFuncSetAttribute(gemm_conv<256, 8, 2, 8>,
                         cudaFuncAttributeMaxDynamicSharedMemorySize, SMEM);

    // weight pack + adjacency build (one launch)
    k_packall<<<3832, 256>>>(w2, w3, w4, w5, wph, ei);

    // L1 direct conv -> a1 (258-grid, C=32)
    conv1_k<<<dim3(16, 16, 2), 256>>>(x, w1, b1, a1 + MARGIN);

    // L2: 32->64, 9 chunks, fused epilogue -> a2
    gemm_conv<32, 5, 0, 1><<<dim3(512, 1), 256, SMEM>>>(
        a1 + MARGIN, wph, b2, a2 + MARGIN, nullptr, 258, 128, 7, 64, 0);

    // L3: 64->128, split-K 2 (9 chunks each) -> partials -> a3
    gemm_conv<64, 6, 2, 2><<<dim3(128, 2, 2), 256, SMEM>>>(
        a2 + MARGIN, wph + 18432, b3, nullptr, D, 130, 64, 6, 128, 16384);
    k_redpool<<<2048, 256>>>(D, b3, a3 + MARGIN, nullptr, 128, 4096, 64, 6, 2, 0);

    // L4: 128->256, split-K 4 (9 chunks each) -> partials -> a4
    gemm_conv<128, 7, 2, 4><<<dim3(32, 4, 4), 256, SMEM>>>(
        a3 + MARGIN, wph + 92160, b4, nullptr, D, 66, 32, 5, 256, 4096);
    k_redpool<<<1024, 256>>>(D, b4, a4 + MARGIN, nullptr, 256, 1024, 32, 5, 4, 0);

    // L5: 256->256, split-K 8 (9 chunks each) -> partials -> org
    gemm_conv<256, 8, 2, 8><<<dim3(8, 4, 8), 256, SMEM>>>(
        a4 + MARGIN, wph + 387072, b5, nullptr, D, 34, 16, 4, 256, 1024);
    k_redpool<<<256, 256>>>(D, b5, nullptr, org, 256, 256, 16, 4, 8, 1);

    // graph stage (adj zeroed by previous replay's k_tmplink; scal by k_final)
    k_rowstage<<<256, 256>>>(org, s1wl, s1wr, s1b, s2wl, s2wr, s2b);
    k_tmplink<<<256, 256>>>();
    k_adjebin<<<128, 128>>>(dout);
    k_final<<<1, 128>>>(s3wl, s3wr, s3b, dout);
}

// round 17
// speedup vs baseline: 1.0787x; 1.0787x over previous
#include <cuda_runtime.h>
#include <cuda_bf16.h>
#include <cuda_fp16.h>
#include <math.h>
#include <stdint.h>

#define NNODE 256
#define NCLUS 128
#define NEDGE 4096
#define MARGIN 32768   // fp16 elems of slack on both sides of activation planes

// ---------------------------------------------------------------------------
// Scratch (device globals). Zero-initialized at module load; pad rings and
// margins are NEVER written. g_adj / g_scal are re-zeroed by their last
// consumers each replay, so every replay starts from the same state.
// ---------------------------------------------------------------------------
__device__ __align__(16) __half g_a1[2228224];   // 258^2*32 + margins
__device__ __align__(16) __half g_a2[1150000];   // 130^2*64 + margins
__device__ __align__(16) __half g_a3[625000];    // 66^2*128 + margins
__device__ __align__(16) __half g_a4[365000];    // 34^2*256 + margins
__device__ __align__(16) __half g_wph[980000];
__device__ __align__(16) float g_D[2097152];     // split-K partials
__device__ float g_org[NNODE * NNODE];
__device__ float g_adj[NNODE * NNODE];
__device__ float g_ssoft[NNODE * NCLUS];
__device__ float g_ssoftT[NCLUS * NNODE];
__device__ float g_x1[NNODE * 2];
__device__ float g_tmp[NNODE * NCLUS];
__device__ float g_nodes[NCLUS * 2];
__device__ float g_ebin[NCLUS * NCLUS];
__device__ float g_scal[2];

// ---------------------------------------------------------------------------
// Warp MMA helpers (plain PTX; works on sm_100 non-'a' target)
// ---------------------------------------------------------------------------
__device__ __forceinline__ void ldsm4(uint32_t* r, uint32_t a) {
    asm volatile("ldmatrix.sync.aligned.m8n8.x4.shared.b16 {%0,%1,%2,%3}, [%4];"
                 : "=r"(r[0]), "=r"(r[1]), "=r"(r[2]), "=r"(r[3]) : "r"(a));
}
__device__ __forceinline__ void mma16816(float* d, const uint32_t* a,
                                         uint32_t b0, uint32_t b1) {
    asm volatile(
        "mma.sync.aligned.m16n8k16.row.col.f32.f16.f16.f32 "
        "{%0,%1,%2,%3}, {%4,%5,%6,%7}, {%8,%9}, {%0,%1,%2,%3};"
        : "+f"(d[0]), "+f"(d[1]), "+f"(d[2]), "+f"(d[3])
        : "r"(a[0]), "r"(a[1]), "r"(a[2]), "r"(a[3]), "r"(b0), "r"(b1));
}
__device__ __forceinline__ uint32_t s2u(const void* p) {
    uint32_t a;
    asm("{ .reg .u64 t; cvta.to.shared.u64 t, %1; cvt.u32.u64 %0, t; }"
        : "=r"(a) : "l"(p));
    return a;
}

// ---------------------------------------------------------------------------
// L1: direct conv 3->32, 512x512, fused bias+relu+pool, padded HWC fp16 out
// ---------------------------------------------------------------------------
__global__ void __launch_bounds__(256, 2)
conv1_k(const float* __restrict__ in, const float* __restrict__ w,
        const float* __restrict__ bias, __half* __restrict__ oh) {
    const int H = 512, W = 512;
    __shared__ float s_in[3 * 1156];
    __shared__ float s_w[3 * 16 * 12];
    const int tid = threadIdx.x, tx = tid & 15, ty = tid >> 4;
    const int ox0 = blockIdx.x * 16, oy0 = blockIdx.y * 16;
    const int co0 = blockIdx.z * 16;
    const int ix0 = 2 * ox0 - 1, iy0 = 2 * oy0 - 1;

    for (int i = tid; i < 16 * 27; i += 256) {
        int co = i / 27, rem = i - co * 27, ci = rem / 9, t = rem - ci * 9;
        s_w[(ci * 16 + co) * 12 + t] = w[((co0 + co) * 3 + ci) * 9 + t];
    }
    for (int ci = 0; ci < 3; ++ci) {
        const float* inp = in + ci * H * W;
        for (int i = tid; i < 1156; i += 256) {
            int r = i / 34, c = i - r * 34;
            int gy = iy0 + r, gx = ix0 + c;
            s_in[ci * 1156 + i] =
                (gy >= 0 && gy < H && gx >= 0 && gx < W) ? inp[gy * W + gx] : 0.f;
        }
    }
    __syncthreads();

    float acc[16][4];
#pragma unroll
    for (int co = 0; co < 16; ++co)
#pragma unroll
        for (int q = 0; q < 4; ++q) acc[co][q] = 0.f;

    const int base = (2 * ty) * 34 + 2 * tx;
#pragma unroll
    for (int ci = 0; ci < 3; ++ci) {
        float p[16];
        const float* sp = s_in + ci * 1156 + base;
#pragma unroll
        for (int r = 0; r < 4; ++r)
#pragma unroll
            for (int c = 0; c < 4; ++c) p[r * 4 + c] = sp[r * 34 + c];
#pragma unroll
        for (int co = 0; co < 16; ++co) {
            const float* wp = &s_w[(ci * 16 + co) * 12];
#pragma unroll
            for (int ky = 0; ky < 3; ++ky)
#pragma unroll
                for (int kx = 0; kx < 3; ++kx) {
                    float wv = wp[ky * 3 + kx];
#pragma unroll
                    for (int dy = 0; dy < 2; ++dy)
#pragma unroll
                        for (int dx = 0; dx < 2; ++dx)
                            acc[co][dy * 2 + dx] += wv * p[(dy + ky) * 4 + (dx + kx)];
                }
        }
    }

    const long pix = ((long)(oy0 + ty + 1) * 258 + (ox0 + tx + 1)) * 32;
#pragma unroll
    for (int co = 0; co < 16; ++co) {
        float m = fmaxf(fmaxf(acc[co][0], acc[co][1]),
                        fmaxf(acc[co][2], acc[co][3]));
        oh[pix + co0 + co] = __float2half(fmaxf(m + bias[co0 + co], 0.f));
    }
}

// ---------------------------------------------------------------------------
// Fused weight pack for w2..w5 (+ adjacency build in trailing blocks).
// ---------------------------------------------------------------------------
__global__ void k_packall(const float* __restrict__ w2, const float* __restrict__ w3,
                          const float* __restrict__ w4, const float* __restrict__ w5,
                          __half* __restrict__ wh, const int* __restrict__ ei) {
    if (blockIdx.x >= 3816) {   // adjacency build (16 blocks)
        int e = (blockIdx.x - 3816) * 256 + threadIdx.x;
        if (e < NEDGE)
            atomicAdd(&g_adj[ei[e] * NNODE + ei[NEDGE + e]], 1.f);
        return;
    }
    int idx = blockIdx.x * 256 + threadIdx.x;
    if (idx >= 976896) return;
    const float* w; int CIN, LGC, base;
    if (idx < 18432)      { w = w2; CIN = 32;  LGC = 5; base = 0; }
    else if (idx < 92160) { w = w3; CIN = 64;  LGC = 6; base = 18432; }
    else if (idx < 387072){ w = w4; CIN = 128; LGC = 7; base = 92160; }
    else                  { w = w5; CIN = 256; LGC = 8; base = 387072; }
    int local = idx - base;
    int KTOT = 9 * CIN;
    int co = local / KTOT, kc = local - co * KTOT;
    int k = kc >> LGC, ci = kc & (CIN - 1);
    wh[idx] = __float2half(w[((size_t)co * CIN + ci) * 9 + k]);
}

// ---------------------------------------------------------------------------
// Implicit-GEMM conv via single fp16 mma.sync, 32-K chunks (measured best).
// OUTM=0: fused bias+relu+pool -> fp16 padded HWC (NS==1)
// OUTM=2: split-K raw fp32 partials -> forg[z][m][n]
// ---------------------------------------------------------------------------
template <int CIN, int LGC, int OUTM, int NS>
__global__ void __launch_bounds__(256, 2)
gemm_conv(const __half* __restrict__ ah, const __half* __restrict__ wh,
          const float* __restrict__ bias,
          __half* __restrict__ oh, float* __restrict__ forg,
          int Wp, int W2, int lg, int coutTot, int mtot) {
    constexpr int KTOT = 9 * CIN;
    constexpr int NCHUNK = KTOT / 32;
    constexpr int NCH = NCHUNK / NS;
    constexpr int ASZ = 128 * 80, BSZ = 64 * 80;
    constexpr int STG = ASZ + BSZ;       // 15360 per stage

    extern __shared__ __align__(16) char smc[];
    const uint32_t sb = s2u(smc);
    const int tid = threadIdx.x, lid = tid & 31, wid = tid >> 5;
    const int wmi = wid & 3, wni = wid >> 2;
    const int p0 = blockIdx.x * 128, n0 = blockIdx.y * 64;
    const int c0 = (NS > 1) ? blockIdx.z * NCH : 0;

    const int arow = tid >> 2, au = tid & 3;
    const uint32_t soA = arow * 80 + au * 16;

    const int mat = lid >> 3, i8 = lid & 7;
    const int mrow0 = wmi * 32 + (mat & 1) * 8 + i8;
    const int nrow0 = wni * 32 + (mat & 1) * 8 + i8;
    const int cu = mat >> 1;

    auto rowbase = [&](int m) -> long {
        int q = m >> 2, dy = (m >> 1) & 1, dx = m & 1;
        int py = q >> lg, px = q & (W2 - 1);
        return ((long)(2 * py + 1 + dy) * Wp + (2 * px + 1 + dx)) * CIN;
    };
    const long rb0 = rowbase(p0 + arow);
    const long rb1 = rowbase(p0 + arow + 64);
    const long wbase = (long)(n0 + arow) * KTOT + au * 8;

    float acc[2][4][4];
#pragma unroll
    for (int t = 0; t < 2; ++t)
#pragma unroll
        for (int j = 0; j < 4; ++j)
#pragma unroll
            for (int q = 0; q < 4; ++q) acc[t][j][q] = 0.f;

    uint4 rg[3];
    auto fetch = [&](int chunk) {
        const int kc0 = chunk * 32;
        const int kc = kc0 + au * 8;
        const int k = kc >> LGC;
        const int ci = kc & (CIN - 1);
        const long nb = ((long)(k / 3 - 1) * Wp + (k % 3 - 1)) * CIN + ci;
        rg[0] = *(const uint4*)(ah + rb0 + nb);
        rg[1] = *(const uint4*)(ah + rb1 + nb);
        rg[2] = *(const uint4*)(wh + wbase + kc0);
    };
    auto store = [&](int s) {
        char* d = smc + s * STG;
        *(uint4*)(d + soA) = rg[0];
        *(uint4*)(d + soA + 64 * 80) = rg[1];
        *(uint4*)(d + ASZ + soA) = rg[2];
    };
    auto compute = [&](int s) {
        const uint32_t base = sb + s * STG;
#pragma unroll
        for (int ks = 0; ks < 2; ++ks) {
            const uint32_t ucol = (ks * 2 + cu) * 16;
            uint32_t fah[2][4], fbh[2][4];
#pragma unroll
            for (int t = 0; t < 2; ++t)
                ldsm4(fah[t], base + (mrow0 + t * 16) * 80 + ucol);
#pragma unroll
            for (int j = 0; j < 2; ++j)
                ldsm4(fbh[j], base + ASZ + (nrow0 + j * 16) * 80 + ucol);
#pragma unroll
            for (int t = 0; t < 2; ++t)
#pragma unroll
                for (int j = 0; j < 2; ++j)
#pragma unroll
                    for (int sbi = 0; sbi < 2; ++sbi)
                        mma16816(acc[t][j * 2 + sbi], fah[t],
                                 fbh[j][sbi], fbh[j][sbi + 2]);
        }
    };

    fetch(c0);
    store(0);
    __syncthreads();
    for (int c = 0; c < NCH; ++c) {
        const bool more = (c + 1 < NCH);
        if (more) fetch(c0 + c + 1);
        compute(c & 1);
        if (more) store((c + 1) & 1);
        __syncthreads();
    }

    if (OUTM == 0) {
        const int cq = (lid & 3) * 2;
        const bool wlane = (lid & 12) == 0;
        const int qsub = lid >> 4;
#pragma unroll
        for (int j = 0; j < 4; ++j) {
            const int co = n0 + wni * 32 + j * 8 + cq;
            const float b0 = bias[co], b1 = bias[co + 1];
#pragma unroll
            for (int t = 0; t < 2; ++t) {
                float v[4];
#pragma unroll
                for (int q = 0; q < 4; ++q) {
                    float x = acc[t][j][q];
                    x = fmaxf(x, __shfl_xor_sync(0xffffffffu, x, 4));
                    x = fmaxf(x, __shfl_xor_sync(0xffffffffu, x, 8));
                    v[q] = x;
                }
                if (wlane) {
                    const int Pb = (p0 >> 2) + wmi * 8 + t * 4 + qsub;
                    float r0 = fmaxf(v[0] + b0, 0.f);
                    float r1 = fmaxf(v[1] + b1, 0.f);
                    float r2 = fmaxf(v[2] + b0, 0.f);
                    float r3 = fmaxf(v[3] + b1, 0.f);
                    int py = Pb >> lg, px = Pb & (W2 - 1);
                    long o = ((long)(py + 1) * (W2 + 2) + px + 1) * coutTot + co;
                    oh[o] = __float2half(r0);
                    oh[o + 1] = __float2half(r1);
                    int P2 = Pb + 2;
                    int py2 = P2 >> lg, px2 = P2 & (W2 - 1);
                    long o2 = ((long)(py2 + 1) * (W2 + 2) + px2 + 1) * coutTot + co;
                    oh[o2] = __float2half(r2);
                    oh[o2 + 1] = __float2half(r3);
                }
            }
        }
    } else {
        const int r = lid >> 2, cq = (lid & 3) * 2;
        float* dp = forg + (long)blockIdx.z * mtot * coutTot;
#pragma unroll
        for (int t = 0; t < 2; ++t) {
            const long row = p0 + wmi * 32 + t * 16 + r;
#pragma unroll
            for (int j = 0; j < 4; ++j) {
                float* bp = dp + row * coutTot + n0 + wni * 32 + j * 8 + cq;
                *(float2*)bp = make_float2(acc[t][j][0], acc[t][j][1]);
                *(float2*)(bp + 8L * coutTot) = make_float2(acc[t][j][2], acc[t][j][3]);
            }
        }
    }
}

// ---------------------------------------------------------------------------
// Split-K reduce + pool + bias + relu (outm=0 fp16 HWC; outm=1 fp32 org)
// ---------------------------------------------------------------------------
__global__ void __launch_bounds__(256)
k_redpool(const float* __restrict__ D, const float* __restrict__ bias,
          __half* __restrict__ oh, float* __restrict__ org,
          int cout, int npix, int W2, int lg, int ns, int outm) {
    int idx = blockIdx.x * 256 + threadIdx.x;
    if (idx >= npix * cout) return;
    int co = idx & (cout - 1);
    int q = idx / cout;
    long Mtot = (long)npix * 4;
    float v[4];
#pragma unroll
    for (int k = 0; k < 4; ++k) {
        float s = 0.f;
        for (int z = 0; z < ns; ++z)
            s += D[z * Mtot * cout + (long)(4 * q + k) * cout + co];
        v[k] = s;
    }
    float m = fmaxf(fmaxf(v[0], v[1]), fmaxf(v[2], v[3]));
    float r = fmaxf(m + bias[co], 0.f);
    if (outm == 0) {
        int py = q >> lg, px = q & (W2 - 1);
        oh[((long)(py + 1) * (W2 + 2) + px + 1) * cout + co] = __float2half(r);
    } else {
        org[co * 256 + q] = r;
    }
}

// ---------------------------------------------------------------------------
// Graph stage
// ---------------------------------------------------------------------------

// Fused per-node-row stage: sparse mean-agg -> SAGE2+softmax+entropy -> SAGE1.
__global__ void __launch_bounds__(256)
k_rowstage(const float* __restrict__ org,
           const float* __restrict__ wl1, const float* __restrict__ wr1,
           const float* __restrict__ b1v,
           const float* __restrict__ wl2, const float* __restrict__ wr2,
           const float* __restrict__ b2v) {
    __shared__ float sAgg[256], sOrg[256], sv[256], red[128], sx[4];
    const int i = blockIdx.x, t = threadIdx.x;
    sOrg[t] = org[i * 256 + t];
    float tot = 0.f, cnt = 0.f;
    for (int s = 0; s < 256; ++s) {
        float a = g_adj[s * 256 + i];   // broadcast load
        if (a != 0.f) {
            tot += a * org[s * 256 + t];
            cnt += a;
        }
    }
    sAgg[t] = (cnt > 0.f) ? tot / cnt : 0.f;
    __syncthreads();

    const int j = t & 127, h = t >> 7;
    float v = 0.f;
    for (int k = h * 128; k < h * 128 + 128; ++k)
        v += sAgg[k] * wl2[k * 128 + j] + sOrg[k] * wr2[k * 128 + j];
    sv[t] = v;
    __syncthreads();

    float lv = (t < 128) ? sv[t] + sv[t + 128] + b2v[t] : -1e30f;
    if (t >= 128 && t < 132) {
        int jj = (t - 128) & 1, hh = (t - 128) >> 1;
        float xv = 0.f;
        for (int k = hh * 128; k < hh * 128 + 128; ++k)
            xv += sAgg[k] * wl1[k * 2 + jj] + sOrg[k] * wr1[k * 2 + jj];
        sx[t - 128] = xv;
    }

    if (t < 128) red[t] = lv;
    __syncthreads();
    for (int off = 64; off > 0; off >>= 1) {
        if (t < off) red[t] = fmaxf(red[t], red[t + off]);
        __syncthreads();
    }
    float m = red[0];
    __syncthreads();
    float e = (t < 128) ? expf(lv - m) : 0.f;
    if (t < 128) red[t] = e;
    __syncthreads();
    for (int off = 64; off > 0; off >>= 1) {
        if (t < off) red[t] += red[t + off];
        __syncthreads();
    }
    float denom = red[0];
    __syncthreads();
    float p = e / denom;
    if (t < 128) {
        g_ssoft[i * 128 + t] = p;
        g_ssoftT[t * 256 + i] = p;
        red[t] = -p * logf(p + 1e-15f);
    }
    __syncthreads();
    for (int off = 64; off > 0; off >>= 1) {
        if (t < off) red[t] += red[t + off];
        __syncthreads();
    }
    if (t == 0) atomicAdd(&g_scal[1], red[0]);
    if (t < 2) g_x1[i * 2 + t] = sx[t] + sx[t + 2] + b1v[t];
}

// Fused: tmp row i (sparse adj@ssoft) + link-loss row i (coalesced via ssoftT);
// zeroes adj row i for the next replay.
__global__ void __launch_bounds__(256) k_tmplink() {
    __shared__ float rowA[256], rowS[128], red[256];
    const int i = blockIdx.x, t = threadIdx.x;
    rowA[t] = g_adj[i * NNODE + t];
    if (t < 128) rowS[t] = g_ssoft[i * NCLUS + t];
    __syncthreads();
    g_adj[i * NNODE + t] = 0.f;   // self-clean for next replay

    float d = 0.f;
    for (int c = 0; c < NCLUS; ++c)
        d += rowS[c] * g_ssoftT[c * 256 + t];
    float diff = rowA[t] - d;
    red[t] = diff * diff;

    if (t < 128) {
        float v = 0.f;
        for (int k = 0; k < NNODE; ++k) {
            float a = rowA[k];
            if (a != 0.f) v += a * g_ssoft[k * NCLUS + t];
        }
        g_tmp[i * NCLUS + t] = v;
    }
    __syncthreads();
    for (int off = 128; off > 0; off >>= 1) {
        if (t < off) red[t] += red[t + off];
        __syncthreads();
    }
    if (t == 0) atomicAdd(&g_scal[0], red[0]);
}

// Fused: adjpool row r -> rowmax -> edge_bin; + xpool column r -> nodes
__global__ void __launch_bounds__(128) k_adjebin(float* __restrict__ dout) {
    const int r = blockIdx.x, c = threadIdx.x;
    float v = 0.f;
    for (int i = 0; i < NNODE; ++i)
        v += g_ssoftT[r * 256 + i] * g_tmp[i * NCLUS + c];
    __shared__ float red[128], r0[128], r1[128];
    float p0 = 0.f, p1 = 0.f;
    for (int i = c; i < NNODE; i += 128) {
        float s = g_ssoftT[r * 256 + i];
        p0 += s * g_x1[i * 2];
        p1 += s * g_x1[i * 2 + 1];
    }
    r0[c] = p0; r1[c] = p1;
    red[c] = v;
    __syncthreads();
    for (int off = 64; off > 0; off >>= 1) {
        if (c < off) {
            red[c] = fmaxf(red[c], red[c + off]);
            r0[c] += r0[c + off];
            r1[c] += r1[c + off];
        }
        __syncthreads();
    }
    float eb = (v == red[0]) ? 1.f : 0.f;
    g_ebin[r * NCLUS + c] = eb;
    dout[514 + r * NCLUS + c] = eb;
    if (c == 0) {
        float n0 = tanhf(r0[0]), n1 = tanhf(r1[0]);
        g_nodes[r * 2] = n0; g_nodes[r * 2 + 1] = n1;
        dout[258 + r * 2] = n0; dout[258 + r * 2 + 1] = n1;
    }
}

__global__ void __launch_bounds__(128) k_final(const float* __restrict__ wl,
                                               const float* __restrict__ wr,
                                               const float* __restrict__ bb,
                                               float* __restrict__ dout) {
    int c = threadIdx.x;
    float ind = 0.f, a0 = 0.f, a1 = 0.f;
    for (int r = 0; r < NCLUS; ++r) {
        float e = g_ebin[r * NCLUS + c];
        ind += e;
        a0 += e * g_nodes[r * 2];
        a1 += e * g_nodes[r * 2 + 1];
    }
    if (ind > 0.f) { a0 /= ind; a1 /= ind; } else { a0 = 0.f; a1 = 0.f; }
    float n0 = g_nodes[c * 2], n1 = g_nodes[c * 2 + 1];
#pragma unroll
    for (int j = 0; j < 2; ++j) {
        float o = a0 * wl[j] + a1 * wl[2 + j] + bb[j] + n0 * wr[j] + n1 * wr[2 + j];
        dout[c * 2 + j] = o;
    }
    if (c == 0) {
        dout[256] = sqrtf(g_scal[0]) / 65536.f;
        dout[257] = g_scal[1] / 256.f;
        g_scal[0] = 0.f;   // self-clean for next replay
        g_scal[1] = 0.f;
    }
}

// ---------------------------------------------------------------------------
extern "C" void kernel_launch(void* const* d_in, const int* in_sizes, int n_in,
                              void* d_out, int out_size) {
    const float* x    = (const float*)d_in[0];
    const int*   ei   = (const int*)d_in[1];
    const float* w1   = (const float*)d_in[2];
    const float* b1   = (const float*)d_in[3];
    const float* w2   = (const float*)d_in[4];
    const float* b2   = (const float*)d_in[5];
    const float* w3   = (const float*)d_in[6];
    const float* b3   = (const float*)d_in[7];
    const float* w4   = (const float*)d_in[8];
    const float* b4   = (const float*)d_in[9];
    const float* w5   = (const float*)d_in[10];
    const float* b5   = (const float*)d_in[11];
    const float* s1wl = (const float*)d_in[12];
    const float* s1wr = (const float*)d_in[13];
    const float* s1b  = (const float*)d_in[14];
    const float* s2wl = (const float*)d_in[15];
    const float* s2wr = (const float*)d_in[16];
    const float* s2b  = (const float*)d_in[17];
    const float* s3wl = (const float*)d_in[18];
    const float* s3wr = (const float*)d_in[19];
    const float* s3b  = (const float*)d_in[20];
    float* dout = (float*)d_out;

    __half *a1, *a2, *a3, *a4, *wph;
    float *org, *D;
    cudaGetSymbolAddress((void**)&a1, g_a1);
    cudaGetSymbolAddress((void**)&a2, g_a2);
    cudaGetSymbolAddress((void**)&a3, g_a3);
    cudaGetSymbolAddress((void**)&a4, g_a4);
    cudaGetSymbolAddress((void**)&wph, g_wph);
    cudaGetSymbolAddress((void**)&org, g_org);
    cudaGetSymbolAddress((void**)&D, g_D);

    const int SMEM = 2 * (128 * 80 + 64 * 80);   // 30720 (2 stages)
    cudaFuncSetAttribute(gemm_conv<32, 5, 0, 1>,
                         cudaFuncAttributeMaxDynamicSharedMemorySize, SMEM);
    cudaFuncSetAttribute(gemm_conv<64, 6, 0, 1>,
                         cudaFuncAttributeMaxDynamicSharedMemorySize, SMEM);
    cudaFuncSetAttribute(gemm_conv<128, 7, 2, 2>,
                         cudaFuncAttributeMaxDynamicSharedMemorySize, SMEM);
    cudaFuncSetAttribute(gemm_conv<256, 8, 2, 4>,
                         cudaFuncAttributeMaxDynamicSharedMemorySize, SMEM);

    // weight pack + adjacency build (one launch)
    k_packall<<<3832, 256>>>(w2, w3, w4, w5, wph, ei);

    // L1 direct conv -> a1 (258-grid, C=32)
    conv1_k<<<dim3(16, 16, 2), 256>>>(x, w1, b1, a1 + MARGIN);

    // L2: 32->64 -> a2 (fused epilogue)
    gemm_conv<32, 5, 0, 1><<<dim3(512, 1), 256, SMEM>>>(
        a1 + MARGIN, wph, b2, a2 + MARGIN, nullptr, 258, 128, 7, 64, 0);

    // L3: 64->128 -> a3 (fused epilogue)
    gemm_conv<64, 6, 0, 1><<<dim3(128, 2), 256, SMEM>>>(
        a2 + MARGIN, wph + 18432, b3, a3 + MARGIN, nullptr, 130, 64, 6, 128, 0);

    // L4: 128->256, split-K 2 -> partials -> a4
    gemm_conv<128, 7, 2, 2><<<dim3(32, 4, 2), 256, SMEM>>>(
        a3 + MARGIN, wph + 92160, b4, nullptr, D, 66, 32, 5, 256, 4096);
    k_redpool<<<1024, 256>>>(D, b4, a4 + MARGIN, nullptr, 256, 1024, 32, 5, 2, 0);

    // L5: 256->256, split-K 4 -> partials -> org
    gemm_conv<256, 8, 2, 4><<<dim3(8, 4, 4), 256, SMEM>>>(
        a4 + MARGIN, wph + 387072, b5, nullptr, D, 34, 16, 4, 256, 1024);
    k_redpool<<<256, 256>>>(D, b5, nullptr, org, 256, 256, 16, 4, 4, 1);

    // graph stage (adj zeroed by previous replay's k_tmplink; scal by k_final)
    k_rowstage<<<256, 256>>>(org, s1wl, s1wr, s1b, s2wl, s2wr, s2b);
    k_tmplink<<<256, 256>>>();
    k_adjebin<<<128, 128>>>(dout);
    k_final<<<1, 128>>>(s3wl, s3wr, s3b, dout);
}